// round 1
// baseline (speedup 1.0000x reference)
#include <cuda_runtime.h>
#include <cuda_bf16.h>

#define NF      2048
#define NROWS   8192
#define RCHUNKS 128
#define RPC     (NROWS / RCHUNKS)   // 64 rows per chunk

// Scratch (allocation-free): partial sums/sumsqs + final stats
__device__ float g_psum[RCHUNKS * NF];
__device__ float g_psq [RCHUNKS * NF];
__device__ float g_mean[NF];
__device__ float g_istd[NF];

// Pass 1: each block = (1024 columns) x (64 rows) partial sum / sumsq.
// Threads own 4 consecutive columns (float4) -> fully coalesced 128B segments.
__global__ void __launch_bounds__(256) k_partial(const float* __restrict__ x) {
    const int col   = (blockIdx.x * 256 + threadIdx.x) * 4;  // blockIdx.x in [0,2)
    const int chunk = blockIdx.y;                            // [0,128)
    const float4* xp = reinterpret_cast<const float4*>(
        x + (size_t)chunk * RPC * NF + col);

    float4 s = make_float4(0.f, 0.f, 0.f, 0.f);
    float4 q = make_float4(0.f, 0.f, 0.f, 0.f);
    #pragma unroll 8
    for (int r = 0; r < RPC; ++r) {
        float4 v = xp[(size_t)r * (NF / 4)];
        s.x += v.x;       s.y += v.y;       s.z += v.z;       s.w += v.w;
        q.x += v.x * v.x; q.y += v.y * v.y; q.z += v.z * v.z; q.w += v.w * v.w;
    }
    *reinterpret_cast<float4*>(g_psum + chunk * NF + col) = s;
    *reinterpret_cast<float4*>(g_psq  + chunk * NF + col) = q;
}

// Pass 2: one thread per column, reduce 128 partials in double (fixed order,
// deterministic). var = (sumsq - N*mean^2)/(N-1)  (ddof=1, matches Welford).
__global__ void __launch_bounds__(256) k_finish() {
    const int col = blockIdx.x * 256 + threadIdx.x;  // 8 blocks x 256 = 2048
    double s = 0.0, q = 0.0;
    #pragma unroll 8
    for (int k = 0; k < RCHUNKS; ++k) {
        s += (double)g_psum[k * NF + col];
        q += (double)g_psq [k * NF + col];
    }
    const double mean = s / (double)NROWS;
    const double var  = (q - s * mean) / (double)(NROWS - 1);
    g_mean[col] = (float)mean;
    g_istd[col] = (float)(1.0 / sqrt(var + 1e-6));
}

// Pass 3: out = (x - mean[col]) * istd[col], float4 streaming.
__global__ void __launch_bounds__(256) k_norm(const float* __restrict__ x,
                                              float* __restrict__ out) {
    const size_t i  = (size_t)blockIdx.x * 256 + threadIdx.x;  // float4 index
    const int   col = (int)((i * 4) & (NF - 1));
    float4 v = reinterpret_cast<const float4*>(x)[i];
    float4 m = *reinterpret_cast<const float4*>(g_mean + col);
    float4 t = *reinterpret_cast<const float4*>(g_istd + col);
    float4 o;
    o.x = (v.x - m.x) * t.x;
    o.y = (v.y - m.y) * t.y;
    o.z = (v.z - m.z) * t.z;
    o.w = (v.w - m.w) * t.w;
    reinterpret_cast<float4*>(out)[i] = o;
}

extern "C" void kernel_launch(void* const* d_in, const int* in_sizes, int n_in,
                              void* d_out, int out_size) {
    const float* x = (const float*)d_in[0];   // [8192, 2048] fp32
    float* out = (float*)d_out;               // [8192, 2048] fp32

    k_partial<<<dim3(NF / 1024, RCHUNKS), 256>>>(x);
    k_finish <<<NF / 256, 256>>>();
    k_norm   <<<(NROWS * NF / 4) / 256, 256>>>(x, out);
}

// round 3
// speedup vs baseline: 2.0488x; 2.0488x over previous
#include <cuda_runtime.h>
#include <cuda_bf16.h>

#define NF      2048
#define NROWS   8192
#define RCHUNKS 512
#define RPC     (NROWS / RCHUNKS)   // 16 rows per chunk

// Scratch (allocation-free): partial sums/sumsqs + final stats
__device__ float g_psum[RCHUNKS * NF];   // 4 MiB
__device__ float g_psq [RCHUNKS * NF];   // 4 MiB
__device__ float g_mean[NF];
__device__ float g_istd[NF];

// ---------------------------------------------------------------------------
// Pass 1: each block = (1024 columns) x (16 rows) partial sum / sumsq.
// grid (2, 512) = 1024 blocks -> ~7 CTAs/SM for deep MLP.
// Threads own 4 consecutive columns (float4) -> fully coalesced 128B segments.
// ---------------------------------------------------------------------------
__global__ void __launch_bounds__(256) k_partial(const float* __restrict__ x) {
    const int col   = (blockIdx.x * 256 + threadIdx.x) * 4;
    const int chunk = blockIdx.y;
    const float4* xp = reinterpret_cast<const float4*>(
        x + (size_t)chunk * RPC * NF + col);

    float4 s = make_float4(0.f, 0.f, 0.f, 0.f);
    float4 q = make_float4(0.f, 0.f, 0.f, 0.f);
    #pragma unroll
    for (int r = 0; r < RPC; ++r) {
        float4 v = xp[(size_t)r * (NF / 4)];   // default policy: keep in L2 for pass 3
        s.x += v.x;       s.y += v.y;       s.z += v.z;       s.w += v.w;
        q.x += v.x * v.x; q.y += v.y * v.y; q.z += v.z * v.z; q.w += v.w * v.w;
    }
    *reinterpret_cast<float4*>(g_psum + chunk * NF + col) = s;
    *reinterpret_cast<float4*>(g_psq  + chunk * NF + col) = q;
}

// ---------------------------------------------------------------------------
// Pass 2: 64 blocks x 256 threads. Each block owns 32 columns; 8 threads per
// column each sum 64 partials (coalesced: consecutive threads -> consecutive
// columns), then a fixed-order shared-memory combine. Deterministic.
// var = (sumsq - N*mean^2)/(N-1)  (ddof=1, matches sequential Welford).
// ---------------------------------------------------------------------------
__global__ void __launch_bounds__(256) k_finish() {
    __shared__ float ssum[256];
    __shared__ float ssq [256];
    const int t = threadIdx.x;
    const int c = blockIdx.x * 32 + (t & 31);   // column
    const int j = t >> 5;                       // partial-segment index [0,8)

    float s = 0.f, q = 0.f;
    #pragma unroll 8
    for (int k = j * 64; k < j * 64 + 64; ++k) {
        s += g_psum[k * NF + c];
        q += g_psq [k * NF + c];
    }
    ssum[t] = s;
    ssq [t] = q;
    __syncthreads();

    if (j == 0) {
        double S = 0.0, Q = 0.0;
        #pragma unroll
        for (int jj = 0; jj < 8; ++jj) {
            S += (double)ssum[jj * 32 + (t & 31)];
            Q += (double)ssq [jj * 32 + (t & 31)];
        }
        const double mean = S / (double)NROWS;
        const double var  = (Q - S * mean) / (double)(NROWS - 1);
        g_mean[c] = (float)mean;
        g_istd[c] = (float)(1.0 / sqrt(var + 1e-6));
    }
}

// ---------------------------------------------------------------------------
// Pass 3: out = (x - mean[col]) * istd[col], float4 streaming.
// x was fully streamed through L2 in pass 1 (64 MiB < 126 MiB L2):
//   __ldcs on x   -> evict-first after the last use
//   __stcs on out -> evict-first so the write stream doesn't evict unread x
// ---------------------------------------------------------------------------
__global__ void __launch_bounds__(256) k_norm(const float* __restrict__ x,
                                              float* __restrict__ out) {
    const size_t i  = (size_t)blockIdx.x * 256 + threadIdx.x;  // float4 index
    const int   col = (int)((i * 4) & (NF - 1));
    float4 v = __ldcs(reinterpret_cast<const float4*>(x) + i);
    float4 m = *reinterpret_cast<const float4*>(g_mean + col);
    float4 t = *reinterpret_cast<const float4*>(g_istd + col);
    float4 o;
    o.x = (v.x - m.x) * t.x;
    o.y = (v.y - m.y) * t.y;
    o.z = (v.z - m.z) * t.z;
    o.w = (v.w - m.w) * t.w;
    __stcs(reinterpret_cast<float4*>(out) + i, o);
}

extern "C" void kernel_launch(void* const* d_in, const int* in_sizes, int n_in,
                              void* d_out, int out_size) {
    const float* x = (const float*)d_in[0];   // [8192, 2048] fp32
    float* out = (float*)d_out;               // [8192, 2048] fp32

    k_partial<<<dim3(NF / 1024, RCHUNKS), 256>>>(x);
    k_finish <<<NF / 32, 256>>>();
    k_norm   <<<(NROWS * (NF / 4)) / 256, 256>>>(x, out);
}